// round 9
// baseline (speedup 1.0000x reference)
#include <cuda_runtime.h>
#include <cuda_bf16.h>
#include <math.h>
#include <stdint.h>

// Problem dims
#define SQ   2048
#define DM   1024
#define NH   16
#define DK   64
#define BB   2
#define ROWS (BB*SQ)   // 4096
#define BHN  (BB*NH)   // 32

// ---------------- scratch (static device memory; no allocs allowed) ----------------
__device__ float g_Q  [ (size_t)ROWS*DM ];
__device__ float g_K  [ (size_t)ROWS*DM ];
__device__ float g_V  [ (size_t)ROWS*DM ];
__device__ float g_ctx[ (size_t)ROWS*DM ];
__device__ float g_fc [ (size_t)ROWS*DM ];
__device__ float g_attn[ (size_t)BHN*SQ*SQ ];            // attn dump when not in d_out
__device__ uint32_t g_maskbits[ (size_t)BB*SQ*SQ/32 ];   // 1 bit per (b,q,k)
__device__ int   g_maskmode;

// ---------------- mask dtype detection ----------------
__global__ void detect_mask_kernel(const void* __restrict__ mask)
{
    __shared__ int ok[3];
    int tid = threadIdx.x;
    if (tid < 3) ok[tid] = 1;
    __syncthreads();
    const unsigned int*   pi = (const unsigned int*)mask;
    const unsigned short* ps = (const unsigned short*)mask;
    bool i32ok = true, f32ok = true, bfok = true;
    for (int i = tid; i < 4096; i += 256) {
        unsigned int v = pi[i];
        if (v > 1u) i32ok = false;
        if (v != 0u && v != 0x3F800000u) f32ok = false;
    }
    for (int i = tid; i < 4096; i += 256) {
        unsigned short v = ps[i];
        if (v != 0 && v != 0x3F80) bfok = false;
    }
    if (!i32ok) atomicAnd(&ok[0], 0);
    if (!f32ok) atomicAnd(&ok[1], 0);
    if (!bfok)  atomicAnd(&ok[2], 0);
    __syncthreads();
    if (tid == 0)
        g_maskmode = ok[0] ? 0 : (ok[1] ? 1 : (ok[2] ? 3 : 2));
}

__device__ __forceinline__ bool mask_at(const void* __restrict__ mask, size_t idx, int mode)
{
    if (mode == 0) return ((const int*)mask)[idx] != 0;
    if (mode == 1) return ((const float*)mask)[idx] != 0.0f;
    if (mode == 2) return ((const unsigned char*)mask)[idx] != 0;
    return ((const unsigned short*)mask)[idx] != 0;
}

// mask -> bitmap: one warp per 32-bit word, ballot
__global__ void __launch_bounds__(256) mask_to_bits(const void* __restrict__ mask)
{
    const int w = blockIdx.x * 8 + (threadIdx.x >> 5);
    const int lane = threadIdx.x & 31;
    const int mode = g_maskmode;
    size_t idx = (size_t)w * 32 + lane;
    bool m = mask_at(mask, idx, mode);
    uint32_t bits = __ballot_sync(0xffffffffu, m);
    if (lane == 0) g_maskbits[w] = bits;
}

// ======================= helpers =======================
__device__ __forceinline__ uint32_t smem_u32(const void* p) {
    uint32_t a;
    asm("{ .reg .u64 t; cvta.to.shared.u64 t, %1; cvt.u32.u64 %0, t; }" : "=r"(a) : "l"(p));
    return a;
}
__device__ __forceinline__ uint32_t swz64(uint32_t b)  { return b ^ ((b >> 3) & 0x30); }
__device__ __forceinline__ uint32_t swz128(uint32_t b) { return b ^ ((b >> 3) & 0x70); }

// split f32 -> bf16 hi + bf16 lo
__device__ __forceinline__ void split4(float4 v, uint2& uh, uint2& ul)
{
    __nv_bfloat16 hx = __float2bfloat16(v.x), hy = __float2bfloat16(v.y);
    __nv_bfloat16 hz = __float2bfloat16(v.z), hw = __float2bfloat16(v.w);
    __nv_bfloat16 lx = __float2bfloat16(v.x - __bfloat162float(hx));
    __nv_bfloat16 ly = __float2bfloat16(v.y - __bfloat162float(hy));
    __nv_bfloat16 lz = __float2bfloat16(v.z - __bfloat162float(hz));
    __nv_bfloat16 lw = __float2bfloat16(v.w - __bfloat162float(hw));
    union { __nv_bfloat162 b2[2]; uint2 u; } th, tl;
    th.b2[0] = __halves2bfloat162(hx, hy); th.b2[1] = __halves2bfloat162(hz, hw);
    tl.b2[0] = __halves2bfloat162(lx, ly); tl.b2[1] = __halves2bfloat162(lz, lw);
    uh = th.u; ul = tl.u;
}
__device__ __forceinline__ uint32_t pack_hilo(float x, float y, uint32_t& lo)
{
    __nv_bfloat16 hx = __float2bfloat16(x), hy = __float2bfloat16(y);
    __nv_bfloat16 lx = __float2bfloat16(x - __bfloat162float(hx));
    __nv_bfloat16 ly = __float2bfloat16(y - __bfloat162float(hy));
    union { __nv_bfloat162 b; uint32_t u; } uh, ul;
    uh.b = __halves2bfloat162(hx, hy); ul.b = __halves2bfloat162(lx, ly);
    lo = ul.u; return uh.u;
}

#define LDMX4(r, addr) \
    asm volatile("ldmatrix.sync.aligned.m8n8.x4.shared.b16 {%0,%1,%2,%3}, [%4];" \
        : "=r"((r)[0]), "=r"((r)[1]), "=r"((r)[2]), "=r"((r)[3]) : "r"(addr))

#define MMA_BF16(cc, a, b0_, b1_) \
    asm volatile("mma.sync.aligned.m16n8k16.row.col.f32.bf16.bf16.f32 " \
        "{%0,%1,%2,%3}, {%4,%5,%6,%7}, {%8,%9}, {%0,%1,%2,%3};" \
        : "+f"((cc)[0]), "+f"((cc)[1]), "+f"((cc)[2]), "+f"((cc)[3]) \
        : "r"((a)[0]), "r"((a)[1]), "r"((a)[2]), "r"((a)[3]), "r"(b0_), "r"(b1_))

// ======================= dense bf16x3 GEMM (unchanged from R6, MODE 0 only) ==========
__global__ void __launch_bounds__(256, 2) mma_gemm0(const float* __restrict__ Ap,
                                                    const float* __restrict__ Bp,
                                                    float* __restrict__ Cp)
{
    constexpr int SM_AH = 0, SM_AL = 8192, SM_BH = 16384, SM_BL = 16384 + 8192;
    __shared__ __align__(16) char smem[32768];

    const int tid = threadIdx.x, lane = tid & 31, wid = tid >> 5;
    const int bm = blockIdx.y * 128;
    const int bn = blockIdx.x * 128;

    const float* A = Ap + (size_t)bm * DM;
    const float* Bsrc = Bp + (size_t)bn * DM;
    float* C = Cp;

    const uint32_t sb  = smem_u32(smem);
    const uint32_t sAh = sb + SM_AH, sAl = sb + SM_AL;
    const uint32_t sBh = sb + SM_BH, sBl = sb + SM_BL;

    const int wm = (wid & 3) * 32;
    const int wn = (wid >> 2) * 64;
    const int ar = lane & 15;
    const int ac = (lane >> 4) << 3;
    const int br = (lane & 7) + ((lane & 16) >> 1);
    const int bc = lane & 8;

    float c[2][8][4];
    #pragma unroll
    for (int mi = 0; mi < 2; mi++)
        #pragma unroll
        for (int nf = 0; nf < 8; nf++)
            #pragma unroll
            for (int j = 0; j < 4; j++) c[mi][nf][j] = 0.f;

    for (int it = 0; it < 32; ++it) {
        const int k0g = it * 32;
        __syncthreads();
        {
            const float* src = A + k0g;
            float4 v[4];
            #pragma unroll
            for (int i = 0; i < 4; i++) {
                int idx = tid + (i << 8);
                v[i] = *(const float4*)(src + (size_t)(idx >> 3) * DM + ((idx & 7) << 2));
            }
            #pragma unroll
            for (int i = 0; i < 4; i++) {
                int idx = tid + (i << 8);
                int r = idx >> 3, c4 = (idx & 7) << 2;
                uint2 uh, ul; split4(v[i], uh, ul);
                uint32_t sw = swz64((uint32_t)(r * 64 + (c4 << 1)));
                *(uint2*)(smem + SM_AH + sw) = uh;
                *(uint2*)(smem + SM_AL + sw) = ul;
            }
        }
        {
            const float* src = Bsrc + k0g;
            float4 v[4];
            #pragma unroll
            for (int i = 0; i < 4; i++) {
                int idx = tid + (i << 8);
                v[i] = *(const float4*)(src + (size_t)(idx >> 3) * DM + ((idx & 7) << 2));
            }
            #pragma unroll
            for (int i = 0; i < 4; i++) {
                int idx = tid + (i << 8);
                int r = idx >> 3, c4 = (idx & 7) << 2;
                uint2 uh, ul; split4(v[i], uh, ul);
                uint32_t sw = swz64((uint32_t)(r * 64 + (c4 << 1)));
                *(uint2*)(smem + SM_BH + sw) = uh;
                *(uint2*)(smem + SM_BL + sw) = ul;
            }
        }
        __syncthreads();

        #pragma unroll
        for (int ks = 0; ks < 2; ++ks) {
            uint32_t ah[2][4], al[2][4];
            #pragma unroll
            for (int mi = 0; mi < 2; mi++) {
                uint32_t off = swz64((uint32_t)((wm + mi * 16 + ar) * 64 + (ks * 16 + ac) * 2));
                LDMX4(ah[mi], sAh + off);
                LDMX4(al[mi], sAl + off);
            }
            #pragma unroll
            for (int p = 0; p < 4; p++) {
                uint32_t bh[4], bl[4];
                uint32_t off = swz64((uint32_t)((wn + p * 16 + br) * 64 + (ks * 16 + bc) * 2));
                LDMX4(bh, sBh + off);
                LDMX4(bl, sBl + off);
                #pragma unroll
                for (int hh = 0; hh < 2; hh++) {
                    const int nf = p * 2 + hh;
                    #pragma unroll
                    for (int mi = 0; mi < 2; mi++) {
                        MMA_BF16(c[mi][nf], ah[mi], bh[hh * 2], bh[hh * 2 + 1]);
                        MMA_BF16(c[mi][nf], ah[mi], bl[hh * 2], bl[hh * 2 + 1]);
                        MMA_BF16(c[mi][nf], al[mi], bh[hh * 2], bh[hh * 2 + 1]);
                    }
                }
            }
        }
    }

    #pragma unroll
    for (int mi = 0; mi < 2; mi++) {
        #pragma unroll
        for (int nf = 0; nf < 8; nf++) {
            int row = bm + wm + mi * 16 + (lane >> 2);
            int col = bn + wn + nf * 8 + ((lane & 3) << 1);
            *(float2*)(C + (size_t)row * DM + col)       = make_float2(c[mi][nf][0], c[mi][nf][1]);
            *(float2*)(C + (size_t)(row + 8) * DM + col) = make_float2(c[mi][nf][2], c[mi][nf][3]);
        }
    }
}

// ======================= fused attention =======================
// Per block: 128 q-rows of one (b,h). S=QK^T/8 -> mask -> exp (no max needed:
// scores ~N(0,1)) -> write unnormalized P, accumulate O += P*V (bf16x3),
// then normalize O and the block's attn slice.
#define SM_QH 0
#define SM_QL 16384
#define SM_KH 32768
#define SM_KL 49152
#define SM_VH 65536
#define SM_VL 81920
#define SM_INV 98304
#define SM_TOT (98304 + 512)

__global__ void __launch_bounds__(256, 1) fused_attn(float* __restrict__ attn_dst)
{
    extern __shared__ __align__(16) char smem[];
    const int tid = threadIdx.x, lane = tid & 31, wid = tid >> 5;
    const int qb = blockIdx.x;           // 0..15
    const int bh = blockIdx.y;           // 0..31
    const int b = bh >> 4, h = bh & 15;
    const int bm = qb * 128;

    const float* Qg = g_Q + ((size_t)b * SQ + bm) * DM + h * DK;
    const float* Kg = g_K + (size_t)b * SQ * DM + h * DK;
    const float* Vg = g_V + (size_t)b * SQ * DM + h * DK;
    float* attnp = attn_dst + (size_t)bh * SQ * SQ + (size_t)bm * SQ;
    float* ctxp  = g_ctx + ((size_t)b * SQ + bm) * DM + h * DK;
    const uint32_t* mbits = g_maskbits + ((size_t)b * SQ + bm) * (SQ / 32);

    const uint32_t sb = smem_u32(smem);
    const uint32_t sQh = sb + SM_QH, sQl = sb + SM_QL;
    const uint32_t sKh = sb + SM_KH, sKl = sb + SM_KL;
    const uint32_t sVh = sb + SM_VH, sVl = sb + SM_VL;
    float* sinv = (float*)(smem + SM_INV);

    const int ar = lane & 15;
    const int ac = (lane >> 4) << 3;
    const int br = (lane & 7) + ((lane & 16) >> 1);
    const int bc = lane & 8;
    const int r0 = wid * 16 + (lane >> 2);   // local q row (and +8)

    // ---- load Q tile once: 128 rows x 64 d, hi/lo, SW128 ----
    #pragma unroll
    for (int i = 0; i < 8; i++) {
        int idx = tid + (i << 8);            // 2048 = 128 rows x 16 f4
        int r = idx >> 4, c4 = (idx & 15) << 2;
        float4 v = *(const float4*)(Qg + (size_t)r * DM + c4);
        uint2 uh, ul; split4(v, uh, ul);
        uint32_t sw = swz128((uint32_t)(r * 128 + c4 * 2));
        *(uint2*)(smem + SM_QH + sw) = uh;
        *(uint2*)(smem + SM_QL + sw) = ul;
    }

    float o[8][4];
    #pragma unroll
    for (int nf = 0; nf < 8; nf++)
        #pragma unroll
        for (int j = 0; j < 4; j++) o[nf][j] = 0.f;
    float rsum0 = 0.f, rsum1 = 0.f;

    for (int kb = 0; kb < 16; ++kb) {
        __syncthreads();   // previous iteration's smem reads done
        // ---- K tile: 128 keys x 64 d ----
        {
            const float* src = Kg + (size_t)kb * 128 * DM;
            #pragma unroll
            for (int i = 0; i < 8; i++) {
                int idx = tid + (i << 8);
                int r = idx >> 4, c4 = (idx & 15) << 2;
                float4 v = *(const float4*)(src + (size_t)r * DM + c4);
                uint2 uh, ul; split4(v, uh, ul);
                uint32_t sw = swz128((uint32_t)(r * 128 + c4 * 2));
                *(uint2*)(smem + SM_KH + sw) = uh;
                *(uint2*)(smem + SM_KL + sw) = ul;
            }
        }
        // ---- V tile transposed: Vt[d 0..63][key 0..127], two key-subtiles ----
        {
            const float* src = Vg + (size_t)kb * 128 * DM;
            #pragma unroll
            for (int i = 0; i < 8; i++) {
                int idx = tid + (i << 8);
                int kr = idx >> 4, n4 = (idx & 15) << 2;
                float4 v = *(const float4*)(src + (size_t)kr * DM + n4);
                float f[4] = {v.x, v.y, v.z, v.w};
                int sub = (kr >> 6) * 8192;
                #pragma unroll
                for (int j = 0; j < 4; j++) {
                    __nv_bfloat16 hi = __float2bfloat16(f[j]);
                    __nv_bfloat16 lo = __float2bfloat16(f[j] - __bfloat162float(hi));
                    uint32_t sw = swz128((uint32_t)((n4 + j) * 128 + (kr & 63) * 2)) + sub;
                    *(__nv_bfloat16*)(smem + SM_VH + sw) = hi;
                    *(__nv_bfloat16*)(smem + SM_VL + sw) = lo;
                }
            }
        }
        __syncthreads();

        // ---- S = Q K^T over this 128-key block; warp owns 16 q-rows x 128 keys ----
        float c[16][4];
        #pragma unroll
        for (int nf = 0; nf < 16; nf++)
            #pragma unroll
            for (int j = 0; j < 4; j++) c[nf][j] = 0.f;

        #pragma unroll
        for (int ks = 0; ks < 4; ++ks) {
            uint32_t qh[4], ql[4];
            uint32_t qoff = swz128((uint32_t)((wid * 16 + ar) * 128 + (ks * 16 + ac) * 2));
            LDMX4(qh, sQh + qoff);
            LDMX4(ql, sQl + qoff);
            #pragma unroll
            for (int p = 0; p < 8; p++) {
                uint32_t kh[4], kl[4];
                uint32_t koff = swz128((uint32_t)((p * 16 + br) * 128 + (ks * 16 + bc) * 2));
                LDMX4(kh, sKh + koff);
                LDMX4(kl, sKl + koff);
                #pragma unroll
                for (int hh = 0; hh < 2; hh++) {
                    const int nf = p * 2 + hh;
                    MMA_BF16(c[nf], qh, kh[hh * 2], kh[hh * 2 + 1]);
                    MMA_BF16(c[nf], qh, kl[hh * 2], kl[hh * 2 + 1]);
                    MMA_BF16(c[nf], ql, kh[hh * 2], kh[hh * 2 + 1]);
                }
            }
        }

        // ---- mask, exp, row-sum, write unnormalized P ----
        uint4 m0 = *((const uint4*)(mbits + (size_t)r0 * (SQ / 32)) + kb);
        uint4 m1 = *((const uint4*)(mbits + (size_t)(r0 + 8) * (SQ / 32)) + kb);
        const uint32_t* w0 = (const uint32_t*)&m0;
        const uint32_t* w1 = (const uint32_t*)&m1;
        #pragma unroll
        for (int nf = 0; nf < 16; nf++) {
            int colb = nf * 8 + ((lane & 3) << 1);
            uint32_t wa = w0[nf >> 2], wb = w1[nf >> 2];
            int sh = colb & 31;
            float p0 = (wa >> sh) & 1        ? 0.f : __expf(0.125f * c[nf][0]);
            float p1 = (wa >> (sh + 1)) & 1  ? 0.f : __expf(0.125f * c[nf][1]);
            float p2 = (wb >> sh) & 1        ? 0.f : __expf(0.125f * c[nf][2]);
            float p3 = (wb >> (sh + 1)) & 1  ? 0.f : __expf(0.125f * c[nf][3]);
            rsum0 += p0 + p1; rsum1 += p2 + p3;
            c[nf][0] = p0; c[nf][1] = p1; c[nf][2] = p2; c[nf][3] = p3;
            int col = kb * 128 + colb;
            *(float2*)(attnp + (size_t)r0 * SQ + col)       = make_float2(p0, p1);
            *(float2*)(attnp + (size_t)(r0 + 8) * SQ + col) = make_float2(p2, p3);
        }

        // ---- O += P * V (bf16x3), k-dim = 128 keys of this block ----
        #pragma unroll
        for (int ks2 = 0; ks2 < 8; ++ks2) {
            uint32_t ahf[4], alf[4];
            ahf[0] = pack_hilo(c[2*ks2][0],   c[2*ks2][1],   alf[0]);
            ahf[1] = pack_hilo(c[2*ks2][2],   c[2*ks2][3],   alf[1]);
            ahf[2] = pack_hilo(c[2*ks2+1][0], c[2*ks2+1][1], alf[2]);
            ahf[3] = pack_hilo(c[2*ks2+1][2], c[2*ks2+1][3], alf[3]);
            int sub = (ks2 >> 2) * 8192;
            #pragma unroll
            for (int p2 = 0; p2 < 4; p2++) {
                uint32_t vh[4], vl[4];
                uint32_t voff = swz128((uint32_t)((p2 * 16 + br) * 128 + (((ks2 & 3) * 16) + bc) * 2)) + sub;
                LDMX4(vh, sVh + voff);
                LDMX4(vl, sVl + voff);
                #pragma unroll
                for (int hh = 0; hh < 2; hh++) {
                    const int nf = p2 * 2 + hh;
                    MMA_BF16(o[nf], ahf, vh[hh * 2], vh[hh * 2 + 1]);
                    MMA_BF16(o[nf], ahf, vl[hh * 2], vl[hh * 2 + 1]);
                    MMA_BF16(o[nf], alf, vh[hh * 2], vh[hh * 2 + 1]);
                }
            }
        }
    }

    // ---- finalize: reduce row sums across quad, normalize O, write ctx ----
    rsum0 += __shfl_xor_sync(0xffffffffu, rsum0, 1);
    rsum0 += __shfl_xor_sync(0xffffffffu, rsum0, 2);
    rsum1 += __shfl_xor_sync(0xffffffffu, rsum1, 1);
    rsum1 += __shfl_xor_sync(0xffffffffu, rsum1, 2);
    const float inv0 = 1.0f / rsum0;
    const float inv1 = 1.0f / rsum1;
    #pragma unroll
    for (int nf = 0; nf < 8; nf++) {
        int col = nf * 8 + ((lane & 3) << 1);
        *(float2*)(ctxp + (size_t)r0 * DM + col)       = make_float2(o[nf][0] * inv0, o[nf][1] * inv0);
        *(float2*)(ctxp + (size_t)(r0 + 8) * DM + col) = make_float2(o[nf][2] * inv1, o[nf][3] * inv1);
    }
    if ((lane & 3) == 0) { sinv[r0] = inv0; sinv[r0 + 8] = inv1; }
    __syncthreads();

    // ---- phase 2: normalize this block's attn slice (just-written, L2-hot) ----
    #pragma unroll 4
    for (int i = 0; i < 256; ++i) {
        int f4 = i * 256 + tid;              // 128 rows x 512 f4/row
        int row = f4 >> 9;
        float s = sinv[row];
        float4* ptr = (float4*)(attnp + (size_t)row * SQ) + (f4 & 511);
        float4 v = *ptr;
        v.x *= s; v.y *= s; v.z *= s; v.w *= s;
        *ptr = v;
    }
}

// ---------------- out = LayerNorm(fc + residual), one block per row of 1024 ---------
__global__ void __launch_bounds__(256) add_ln(const float* __restrict__ res, float* __restrict__ dst)
{
    const size_t row = blockIdx.x;
    const float* f = g_fc + row * DM;
    const float* r = res + row * DM;
    float* o = (dst ? dst : g_Q) + row * DM;
    const int tid = threadIdx.x, lane = tid & 31, warp = tid >> 5;
    __shared__ float sm[8];
    float x[4];
    float s = 0.f;
    #pragma unroll
    for (int i = 0; i < 4; i++) { x[i] = f[i * 256 + tid] + r[i * 256 + tid]; s += x[i]; }
    #pragma unroll
    for (int off = 16; off; off >>= 1) s += __shfl_xor_sync(0xffffffffu, s, off);
    if (lane == 0) sm[warp] = s;
    __syncthreads();
    s = sm[lane & 7];
    #pragma unroll
    for (int off = 4; off; off >>= 1) s += __shfl_xor_sync(0xffffffffu, s, off);
    const float mean = s * (1.0f / DM);
    float s2 = 0.f;
    #pragma unroll
    for (int i = 0; i < 4; i++) { float d = x[i] - mean; s2 += d * d; }
    #pragma unroll
    for (int off = 16; off; off >>= 1) s2 += __shfl_xor_sync(0xffffffffu, s2, off);
    __syncthreads();
    if (lane == 0) sm[warp] = s2;
    __syncthreads();
    s2 = sm[lane & 7];
    #pragma unroll
    for (int off = 4; off; off >>= 1) s2 += __shfl_xor_sync(0xffffffffu, s2, off);
    const float inv = rsqrtf(s2 * (1.0f / DM) + 1e-5f);
    #pragma unroll
    for (int i = 0; i < 4; i++) o[i * 256 + tid] = (x[i] - mean) * inv;
}

// ---------------- launch -----------------------------------------------------------
extern "C" void kernel_launch(void* const* d_in, const int* in_sizes, int n_in,
                              void* d_out, int out_size)
{
    const float* iQ  = (const float*)d_in[0];
    const float* iK  = (const float*)d_in[1];
    const float* iV  = (const float*)d_in[2];
    const void*  msk = d_in[3];
    const float* WQ  = (const float*)d_in[4];
    const float* WK  = (const float*)d_in[5];
    const float* WV  = (const float*)d_in[6];
    const float* Wfc = (const float*)d_in[7];
    float* out = (float*)d_out;

    const long long LN_N  = (long long)ROWS * DM;        // 4,194,304
    const long long ATT_N = (long long)BHN * SQ * SQ;    // 134,217,728
    float* attn_out = nullptr;
    float* ln_out   = out;
    if ((long long)out_size >= LN_N + ATT_N) {
        attn_out = out + LN_N;
    } else if ((long long)out_size == ATT_N) {
        attn_out = out;
        ln_out = nullptr;
    }

    void* p;
    cudaGetSymbolAddress(&p, g_Q);    float* pQ    = (float*)p;
    cudaGetSymbolAddress(&p, g_K);    float* pK    = (float*)p;
    cudaGetSymbolAddress(&p, g_V);    float* pV    = (float*)p;
    cudaGetSymbolAddress(&p, g_ctx);  float* pCtx  = (float*)p;
    cudaGetSymbolAddress(&p, g_fc);   float* pFc   = (float*)p;
    cudaGetSymbolAddress(&p, g_attn); float* pAttn = (float*)p;

    static int smem_set = 0;
    if (!smem_set) {
        cudaFuncSetAttribute(fused_attn, cudaFuncAttributeMaxDynamicSharedMemorySize, SM_TOT);
        smem_set = 1;
    }

    detect_mask_kernel<<<1, 256>>>(msk);
    mask_to_bits<<<(BB * SQ * SQ / 32) / 8, 256>>>(msk);

    dim3 gp(DM / 128, ROWS / 128);               // (8, 32)
    mma_gemm0<<<gp, 256>>>(iQ, WQ, pQ);
    mma_gemm0<<<gp, 256>>>(iK, WK, pK);
    mma_gemm0<<<gp, 256>>>(iV, WV, pV);

    float* attn_dst = attn_out ? attn_out : pAttn;
    dim3 ga(SQ / 128, BHN);                      // (16, 32)
    fused_attn<<<ga, 256, SM_TOT>>>(attn_dst);

    mma_gemm0<<<gp, 256>>>(pCtx, Wfc, pFc);

    add_ln<<<(unsigned)ROWS, 256>>>(iQ, ln_out);
}

// round 10
// speedup vs baseline: 1.1851x; 1.1851x over previous
#include <cuda_runtime.h>
#include <cuda_bf16.h>
#include <math.h>
#include <stdint.h>

// Problem dims
#define SQ   2048
#define DM   1024
#define NH   16
#define DK   64
#define BB   2
#define ROWS (BB*SQ)   // 4096
#define BHN  (BB*NH)   // 32

// ---------------- scratch (static device memory; no allocs allowed) ----------------
__device__ float g_Q  [ (size_t)ROWS*DM ];
__device__ float g_K  [ (size_t)ROWS*DM ];
__device__ float g_V  [ (size_t)ROWS*DM ];
__device__ float g_ctx[ (size_t)ROWS*DM ];
__device__ float g_fc [ (size_t)ROWS*DM ];
__device__ float g_attn[ (size_t)BHN*SQ*SQ ];            // attn dump when not in d_out
__device__ uint32_t g_maskbits[ (size_t)BB*SQ*SQ/32 ];   // 1 bit per (b,q,k)
__device__ int   g_maskmode;

// ---------------- mask dtype detection ----------------
__global__ void detect_mask_kernel(const void* __restrict__ mask)
{
    __shared__ int ok[3];
    int tid = threadIdx.x;
    if (tid < 3) ok[tid] = 1;
    __syncthreads();
    const unsigned int*   pi = (const unsigned int*)mask;
    const unsigned short* ps = (const unsigned short*)mask;
    bool i32ok = true, f32ok = true, bfok = true;
    for (int i = tid; i < 4096; i += 256) {
        unsigned int v = pi[i];
        if (v > 1u) i32ok = false;
        if (v != 0u && v != 0x3F800000u) f32ok = false;
    }
    for (int i = tid; i < 4096; i += 256) {
        unsigned short v = ps[i];
        if (v != 0 && v != 0x3F80) bfok = false;
    }
    if (!i32ok) atomicAnd(&ok[0], 0);
    if (!f32ok) atomicAnd(&ok[1], 0);
    if (!bfok)  atomicAnd(&ok[2], 0);
    __syncthreads();
    if (tid == 0)
        g_maskmode = ok[0] ? 0 : (ok[1] ? 1 : (ok[2] ? 3 : 2));
}

__device__ __forceinline__ bool mask_at(const void* __restrict__ mask, size_t idx, int mode)
{
    if (mode == 0) return ((const int*)mask)[idx] != 0;
    if (mode == 1) return ((const float*)mask)[idx] != 0.0f;
    if (mode == 2) return ((const unsigned char*)mask)[idx] != 0;
    return ((const unsigned short*)mask)[idx] != 0;
}

// mask -> bitmap: one warp per 32-bit word, ballot
__global__ void __launch_bounds__(256) mask_to_bits(const void* __restrict__ mask)
{
    const int w = blockIdx.x * 8 + (threadIdx.x >> 5);
    const int lane = threadIdx.x & 31;
    const int mode = g_maskmode;
    size_t idx = (size_t)w * 32 + lane;
    bool m = mask_at(mask, idx, mode);
    uint32_t bits = __ballot_sync(0xffffffffu, m);
    if (lane == 0) g_maskbits[w] = bits;
}

// ======================= helpers =======================
__device__ __forceinline__ uint32_t smem_u32(const void* p) {
    uint32_t a;
    asm("{ .reg .u64 t; cvta.to.shared.u64 t, %1; cvt.u32.u64 %0, t; }" : "=r"(a) : "l"(p));
    return a;
}
__device__ __forceinline__ uint32_t swz64(uint32_t b)  { return b ^ ((b >> 3) & 0x30); }

// split f32 -> bf16 hi + bf16 lo
__device__ __forceinline__ void split4(float4 v, uint2& uh, uint2& ul)
{
    __nv_bfloat16 hx = __float2bfloat16(v.x), hy = __float2bfloat16(v.y);
    __nv_bfloat16 hz = __float2bfloat16(v.z), hw = __float2bfloat16(v.w);
    __nv_bfloat16 lx = __float2bfloat16(v.x - __bfloat162float(hx));
    __nv_bfloat16 ly = __float2bfloat16(v.y - __bfloat162float(hy));
    __nv_bfloat16 lz = __float2bfloat16(v.z - __bfloat162float(hz));
    __nv_bfloat16 lw = __float2bfloat16(v.w - __bfloat162float(hw));
    union { __nv_bfloat162 b2[2]; uint2 u; } th, tl;
    th.b2[0] = __halves2bfloat162(hx, hy); th.b2[1] = __halves2bfloat162(hz, hw);
    tl.b2[0] = __halves2bfloat162(lx, ly); tl.b2[1] = __halves2bfloat162(lz, lw);
    uh = th.u; ul = tl.u;
}

#define LDMX4(r, addr) \
    asm volatile("ldmatrix.sync.aligned.m8n8.x4.shared.b16 {%0,%1,%2,%3}, [%4];" \
        : "=r"((r)[0]), "=r"((r)[1]), "=r"((r)[2]), "=r"((r)[3]) : "r"(addr))

#define MMA_BF16(cc, a, b0_, b1_) \
    asm volatile("mma.sync.aligned.m16n8k16.row.col.f32.bf16.bf16.f32 " \
        "{%0,%1,%2,%3}, {%4,%5,%6,%7}, {%8,%9}, {%0,%1,%2,%3};" \
        : "+f"((cc)[0]), "+f"((cc)[1]), "+f"((cc)[2]), "+f"((cc)[3]) \
        : "r"((a)[0]), "r"((a)[1]), "r"((a)[2]), "r"((a)[3]), "r"(b0_), "r"(b1_))

// ======================= bf16x3 mma.sync GEMM =======================
// MODE 0: dense  C[4096,1024] = A[4096,1024] * B[1024,1024]^T  (both K-major, ld=DM)
// MODE 1: qk     per bh: scores = mask ? -1e9 : (Q K^T)/8 -> g_attn  (bitmap mask)
// MODE 2: pv     per bh: ctx = attn[2048,2048] @ V[2048,64]  (V transposed on load)
template<int MODE>
__global__ void __launch_bounds__(256, 2) mma_gemm(const float* __restrict__ Ap,
                                                   const float* __restrict__ Bp,
                                                   float* __restrict__ Cp)
{
    constexpr int BN    = (MODE == 2) ? 64 : 128;
    constexpr int NSTEP = (MODE == 0) ? 32 : ((MODE == 1) ? 2 : 64);
    constexpr int BNW   = BN / 2;          // per-warp n extent
    constexpr int NF    = BNW / 8;         // n8 fragments per warp
    constexpr int SM_AH = 0;
    constexpr int SM_AL = 8192;
    constexpr int SM_BH = 16384;
    constexpr int SM_BL = SM_BH + BN * 64;

    __shared__ __align__(16) char smem[SM_BH + 2 * BN * 64];

    const int tid = threadIdx.x, lane = tid & 31, wid = tid >> 5;
    const int bm = blockIdx.y * 128;
    const int bn = blockIdx.x * BN;

    int b = 0;
    const float* A; const float* Bsrc; float* C;
    int lda, ldc;
    if (MODE == 0) {
        A = Ap + (size_t)bm * DM; lda = DM;
        Bsrc = Bp + (size_t)bn * DM;
        C = Cp; ldc = DM;
    } else if (MODE == 1) {
        int bh = blockIdx.z; b = bh >> 4; int h = bh & 15;
        A = g_Q + ((size_t)b * SQ + bm) * DM + h * DK; lda = DM;
        Bsrc = g_K + ((size_t)b * SQ + bn) * DM + h * DK;
        C = Cp + (size_t)bh * SQ * SQ; ldc = SQ;
    } else {
        int bh = blockIdx.z; b = bh >> 4; int h = bh & 15;
        A = Ap + (size_t)bh * SQ * SQ + (size_t)bm * SQ; lda = SQ;   // attn
        Bsrc = g_V + (size_t)b * SQ * DM + h * DK;                    // V (k-major rows)
        C = g_ctx + (size_t)b * SQ * DM + h * DK; ldc = DM;
    }

    const uint32_t sb  = smem_u32(smem);
    const uint32_t sAh = sb + SM_AH, sAl = sb + SM_AL;
    const uint32_t sBh = sb + SM_BH, sBl = sb + SM_BL;

    const int wm = (wid & 3) * 32;         // warp m offset within tile
    const int wn = (wid >> 2) * BNW;       // warp n offset within tile
    const int ar = lane & 15;
    const int ac = (lane >> 4) << 3;
    const int br = (lane & 7) + ((lane & 16) >> 1);
    const int bc = lane & 8;

    float c[2][NF][4];
    #pragma unroll
    for (int mi = 0; mi < 2; mi++)
        #pragma unroll
        for (int nf = 0; nf < NF; nf++)
            #pragma unroll
            for (int j = 0; j < 4; j++) c[mi][nf][j] = 0.f;

    for (int it = 0; it < NSTEP; ++it) {
        const int k0g = it * 32;
        __syncthreads();   // previous chunk's compute done before overwrite

        // ---- A tile: 128 rows x 32 f32 -> hi/lo bf16, SW64 swizzled ----
        {
            const float* src = A + k0g;
            float4 v[4];
            #pragma unroll
            for (int i = 0; i < 4; i++) {
                int idx = tid + (i << 8);
                v[i] = *(const float4*)(src + (size_t)(idx >> 3) * lda + ((idx & 7) << 2));
            }
            #pragma unroll
            for (int i = 0; i < 4; i++) {
                int idx = tid + (i << 8);
                int r = idx >> 3, c4 = (idx & 7) << 2;
                uint2 uh, ul; split4(v[i], uh, ul);
                uint32_t sw = swz64((uint32_t)(r * 64 + (c4 << 1)));
                *(uint2*)(smem + SM_AH + sw) = uh;
                *(uint2*)(smem + SM_AL + sw) = ul;
            }
        }
        // ---- B tile ----
        if (MODE != 2) {
            const float* src = Bsrc + k0g;
            float4 v[4];
            #pragma unroll
            for (int i = 0; i < 4; i++) {
                int idx = tid + (i << 8);
                v[i] = *(const float4*)(src + (size_t)(idx >> 3) * DM + ((idx & 7) << 2));
            }
            #pragma unroll
            for (int i = 0; i < 4; i++) {
                int idx = tid + (i << 8);
                int r = idx >> 3, c4 = (idx & 7) << 2;
                uint2 uh, ul; split4(v[i], uh, ul);
                uint32_t sw = swz64((uint32_t)(r * 64 + (c4 << 1)));
                *(uint2*)(smem + SM_BH + sw) = uh;
                *(uint2*)(smem + SM_BL + sw) = ul;
            }
        } else {
            // transpose-load V: B[n][k] = V[k0g+kr][n], 64 n-rows x 32 k-cols
            const float* src = Bsrc + (size_t)k0g * DM;
            #pragma unroll
            for (int i = 0; i < 2; i++) {
                int idx = tid + (i << 8);
                int kr = idx >> 4, n4 = (idx & 15) << 2;
                float4 v = *(const float4*)(src + (size_t)kr * DM + n4);
                float f[4] = {v.x, v.y, v.z, v.w};
                #pragma unroll
                for (int j = 0; j < 4; j++) {
                    __nv_bfloat16 hi = __float2bfloat16(f[j]);
                    __nv_bfloat16 lo = __float2bfloat16(f[j] - __bfloat162float(hi));
                    uint32_t sw = swz64((uint32_t)((n4 + j) * 64 + kr * 2));
                    *(__nv_bfloat16*)(smem + SM_BH + sw) = hi;
                    *(__nv_bfloat16*)(smem + SM_BL + sw) = lo;
                }
            }
        }
        __syncthreads();

        // ---- compute: 2 k16 steps; term-major MMA order to break RAW chains ----
        #pragma unroll
        for (int ks = 0; ks < 2; ++ks) {
            uint32_t ah[2][4], al[2][4];
            #pragma unroll
            for (int mi = 0; mi < 2; mi++) {
                uint32_t off = swz64((uint32_t)((wm + mi * 16 + ar) * 64 + (ks * 16 + ac) * 2));
                LDMX4(ah[mi], sAh + off);
                LDMX4(al[mi], sAl + off);
            }
            #pragma unroll
            for (int p = 0; p < NF / 2; p++) {
                uint32_t bh[4], bl[4];
                uint32_t off = swz64((uint32_t)((wn + p * 16 + br) * 64 + (ks * 16 + bc) * 2));
                LDMX4(bh, sBh + off);
                LDMX4(bl, sBl + off);
                // term 0: Ah*Bh over all 4 accumulators
                #pragma unroll
                for (int hh = 0; hh < 2; hh++)
                    #pragma unroll
                    for (int mi = 0; mi < 2; mi++)
                        MMA_BF16(c[mi][p * 2 + hh], ah[mi], bh[hh * 2], bh[hh * 2 + 1]);
                // term 1: Ah*Bl
                #pragma unroll
                for (int hh = 0; hh < 2; hh++)
                    #pragma unroll
                    for (int mi = 0; mi < 2; mi++)
                        MMA_BF16(c[mi][p * 2 + hh], ah[mi], bl[hh * 2], bl[hh * 2 + 1]);
                // term 2: Al*Bh
                #pragma unroll
                for (int hh = 0; hh < 2; hh++)
                    #pragma unroll
                    for (int mi = 0; mi < 2; mi++)
                        MMA_BF16(c[mi][p * 2 + hh], al[mi], bh[hh * 2], bh[hh * 2 + 1]);
            }
        }
    }

    // ---- epilogue ----
    #pragma unroll
    for (int mi = 0; mi < 2; mi++) {
        int row = bm + wm + mi * 16 + (lane >> 2);
        uint2 wa, wb;
        if (MODE == 1) {
            const uint32_t* mr = g_maskbits + ((size_t)b * SQ + row) * (SQ / 32) + ((bn + wn) >> 5);
            wa = *(const uint2*)mr;
            wb = *(const uint2*)(mr + 8 * (SQ / 32));
        }
        #pragma unroll
        for (int nf = 0; nf < NF; nf++) {
            int lc  = nf * 8 + ((lane & 3) << 1);
            int col = bn + wn + lc;
            float2 v0 = make_float2(c[mi][nf][0], c[mi][nf][1]);
            float2 v1 = make_float2(c[mi][nf][2], c[mi][nf][3]);
            if (MODE == 1) {
                uint32_t w0 = (lc & 32) ? wa.y : wa.x;
                uint32_t w1 = (lc & 32) ? wb.y : wb.x;
                int sh = lc & 31;
                v0.x = (w0 >> sh) & 1       ? -1e9f : v0.x * 0.125f;
                v0.y = (w0 >> (sh + 1)) & 1 ? -1e9f : v0.y * 0.125f;
                v1.x = (w1 >> sh) & 1       ? -1e9f : v1.x * 0.125f;
                v1.y = (w1 >> (sh + 1)) & 1 ? -1e9f : v1.y * 0.125f;
            }
            *(float2*)(C + (size_t)row * ldc + col)       = v0;
            *(float2*)(C + (size_t)(row + 8) * ldc + col) = v1;
        }
    }
}

// ---------------- row softmax over 2048, one block per row --------------------------
__global__ void __launch_bounds__(256) softmax_rows(const float* __restrict__ src,
                                                    float* __restrict__ dst)
{
    const size_t row = blockIdx.x;
    const float* x = src + row * SQ;
    float* y = dst + row * SQ;
    const int tid = threadIdx.x, lane = tid & 31, warp = tid >> 5;
    __shared__ float sm[8];
    float v[8];
    float m = -3.0e38f;
    #pragma unroll
    for (int i = 0; i < 8; i++) { v[i] = x[i * 256 + tid]; m = fmaxf(m, v[i]); }
    #pragma unroll
    for (int o = 16; o; o >>= 1) m = fmaxf(m, __shfl_xor_sync(0xffffffffu, m, o));
    if (lane == 0) sm[warp] = m;
    __syncthreads();
    m = sm[lane & 7];
    #pragma unroll
    for (int o = 4; o; o >>= 1) m = fmaxf(m, __shfl_xor_sync(0xffffffffu, m, o));
    float s = 0.f;
    #pragma unroll
    for (int i = 0; i < 8; i++) { v[i] = expf(v[i] - m); s += v[i]; }
    #pragma unroll
    for (int o = 16; o; o >>= 1) s += __shfl_xor_sync(0xffffffffu, s, o);
    __syncthreads();
    if (lane == 0) sm[warp] = s;
    __syncthreads();
    s = sm[lane & 7];
    #pragma unroll
    for (int o = 4; o; o >>= 1) s += __shfl_xor_sync(0xffffffffu, s, o);
    const float inv = 1.0f / s;
    #pragma unroll
    for (int i = 0; i < 8; i++) y[i * 256 + tid] = v[i] * inv;
}

// ---------------- out = LayerNorm(fc + residual), one block per row of 1024 ---------
__global__ void __launch_bounds__(256) add_ln(const float* __restrict__ res, float* __restrict__ dst)
{
    const size_t row = blockIdx.x;
    const float* f = g_fc + row * DM;
    const float* r = res + row * DM;
    float* o = (dst ? dst : g_Q) + row * DM;
    const int tid = threadIdx.x, lane = tid & 31, warp = tid >> 5;
    __shared__ float sm[8];
    float x[4];
    float s = 0.f;
    #pragma unroll
    for (int i = 0; i < 4; i++) { x[i] = f[i * 256 + tid] + r[i * 256 + tid]; s += x[i]; }
    #pragma unroll
    for (int off = 16; off; off >>= 1) s += __shfl_xor_sync(0xffffffffu, s, off);
    if (lane == 0) sm[warp] = s;
    __syncthreads();
    s = sm[lane & 7];
    #pragma unroll
    for (int off = 4; off; off >>= 1) s += __shfl_xor_sync(0xffffffffu, s, off);
    const float mean = s * (1.0f / DM);
    float s2 = 0.f;
    #pragma unroll
    for (int i = 0; i < 4; i++) { float d = x[i] - mean; s2 += d * d; }
    #pragma unroll
    for (int off = 16; off; off >>= 1) s2 += __shfl_xor_sync(0xffffffffu, s2, off);
    __syncthreads();
    if (lane == 0) sm[warp] = s2;
    __syncthreads();
    s2 = sm[lane & 7];
    #pragma unroll
    for (int off = 4; off; off >>= 1) s2 += __shfl_xor_sync(0xffffffffu, s2, off);
    const float inv = rsqrtf(s2 * (1.0f / DM) + 1e-5f);
    #pragma unroll
    for (int i = 0; i < 4; i++) o[i * 256 + tid] = (x[i] - mean) * inv;
}

// ---------------- launch -----------------------------------------------------------
extern "C" void kernel_launch(void* const* d_in, const int* in_sizes, int n_in,
                              void* d_out, int out_size)
{
    const float* iQ  = (const float*)d_in[0];
    const float* iK  = (const float*)d_in[1];
    const float* iV  = (const float*)d_in[2];
    const void*  msk = d_in[3];
    const float* WQ  = (const float*)d_in[4];
    const float* WK  = (const float*)d_in[5];
    const float* WV  = (const float*)d_in[6];
    const float* Wfc = (const float*)d_in[7];
    float* out = (float*)d_out;

    const long long LN_N  = (long long)ROWS * DM;        // 4,194,304
    const long long ATT_N = (long long)BHN * SQ * SQ;    // 134,217,728
    float* attn_out = nullptr;
    float* ln_out   = out;
    if ((long long)out_size >= LN_N + ATT_N) {
        attn_out = out + LN_N;
    } else if ((long long)out_size == ATT_N) {
        attn_out = out;
        ln_out = nullptr;
    }

    void* p;
    cudaGetSymbolAddress(&p, g_Q);    float* pQ    = (float*)p;
    cudaGetSymbolAddress(&p, g_K);    float* pK    = (float*)p;
    cudaGetSymbolAddress(&p, g_V);    float* pV    = (float*)p;
    cudaGetSymbolAddress(&p, g_ctx);  float* pCtx  = (float*)p;
    cudaGetSymbolAddress(&p, g_fc);   float* pFc   = (float*)p;
    cudaGetSymbolAddress(&p, g_attn); float* pAttn = (float*)p;

    detect_mask_kernel<<<1, 256>>>(msk);
    mask_to_bits<<<(BB * SQ * SQ / 32) / 8, 256>>>(msk);

    dim3 gp(DM / 128, ROWS / 128);               // (8, 32)
    mma_gemm<0><<<gp, 256>>>(iQ, WQ, pQ);
    mma_gemm<0><<<gp, 256>>>(iK, WK, pK);
    mma_gemm<0><<<gp, 256>>>(iV, WV, pV);

    // scores -> g_attn (always scratch; softmax writes the final attn)
    dim3 gs(SQ / 128, SQ / 128, BHN);            // (16, 16, 32)
    mma_gemm<1><<<gs, 256>>>(nullptr, nullptr, pAttn);

    float* attn_dst = attn_out ? attn_out : pAttn;
    softmax_rows<<<(unsigned)(BHN * SQ), 256>>>(pAttn, attn_dst);

    dim3 gv(1, SQ / 128, BHN);                   // (1, 16, 32)
    mma_gemm<2><<<gv, 256>>>(attn_dst, nullptr, nullptr);

    mma_gemm<0><<<gp, 256>>>(pCtx, Wfc, pFc);

    add_ln<<<(unsigned)ROWS, 256>>>(iQ, ln_out);
}